// round 14
// baseline (speedup 1.0000x reference)
#include <cuda_runtime.h>
#include <math.h>

#define TILE    128
#define THREADS 256
#define DTI_FAR 6   // ti-tj >= 6  =>  min(i-j) = 5*128+1 = 641; 2*641 > max|dp|

// Scratch accumulator + completion counter (no device allocation allowed).
__device__ double       g_acc   = 0.0;
__device__ unsigned int g_count = 0u;

// steps = a*(i-j), valid pairs i >= j, s = 0.4*steps.
// NEAR: acc += relu(|d-1.5s|-s); accc += s when d<0; tot = acc - 0.5*accc.
// FAR (i-j >= 641 > |dp|/2): f = 0.2a*(i-j)*1[p_i>=p_j] - d, and sum(-d)
// over the tile is separable via column half-sums.
__global__ __launch_bounds__(THREADS)
void depth_loss_fused(const float* __restrict__ p,
                      const float* __restrict__ z_spacing,
                      const float* __restrict__ nth_slice,
                      float* __restrict__ out,
                      int n, int n_blocks, int n_far, int T)
{
    __shared__ float sm_pc[TILE];    // p[j]
    __shared__ float sm_aux[TILE];   // far: (float)j ; near: -0.4a*j
    __shared__ float sm_red[8];

    const float a   = z_spacing[0] * nth_slice[0];   // STEP == 1.0
    const float A4  = 0.4f * a;
    const float A02 = 0.2f * a;

    const int tid = threadIdx.x;
    const int bid = blockIdx.x;

    float total;

    if (bid < n_far) {
        // ================= FAR tile =================
        // Far tiles (ti-tj >= DTI_FAR) form a triangle of side T' = T-DTI_FAR.
        int t  = bid;
        int tp = (int)((sqrtf(8.0f * (float)t + 1.0f) - 1.0f) * 0.5f);
        while ((tp + 1) * (tp + 2) / 2 <= t) tp++;
        while (tp * (tp + 1) / 2 > t) tp--;
        int tj = t - tp * (tp + 1) / 2;
        int ti = tp + DTI_FAR;

        const int i0 = ti * TILE;
        const int j0 = tj * TILE;

        if (tid < TILE) {
            int jg = j0 + tid;
            sm_pc[tid]  = p[jg];
            sm_aux[tid] = (float)jg;
        }
        __syncthreads();

        // Column half-sums: sm_red[w] = sum of pc over warp w (w=0..3)
        if (tid < TILE) {
            float v = sm_pc[tid];
            #pragma unroll
            for (int off = 16; off > 0; off >>= 1)
                v += __shfl_xor_sync(0xFFFFFFFFu, v, off);
            if ((tid & 31) == 0) sm_red[tid >> 5] = v;
        }
        __syncthreads();

        const int   row  = tid & (TILE - 1);
        const int   half = tid >> 7;          // 0 or 1 -> 64-col half
        const float pr   = p[i0 + row];
        const float igf  = (float)(i0 + row);

        const float4* pc4 = (const float4*)(sm_pc  + half * 64);
        const float4* jf4 = (const float4*)(sm_aux + half * 64);

        float cnt0 = 0.0f, cnt1 = 0.0f, sj0 = 0.0f, sj1 = 0.0f;
        #pragma unroll
        for (int g = 0; g < 16; ++g) {
            float4 pc = pc4[g];
            float4 jf = jf4[g];
            if (pr >= pc.x) { cnt0 += 1.0f; sj0 += jf.x; }
            if (pr >= pc.y) { cnt1 += 1.0f; sj1 += jf.y; }
            if (pr >= pc.z) { cnt0 += 1.0f; sj0 += jf.z; }
            if (pr >= pc.w) { cnt1 += 1.0f; sj1 += jf.w; }
        }
        float cnt = cnt0 + cnt1;   // exact small integers in fp32
        float sj  = sj0 + sj1;     // exact (sums of ints < 2^24)
        float S_half = half ? (sm_red[2] + sm_red[3])
                            : (sm_red[0] + sm_red[1]);
        total = A02 * (igf * cnt - sj) + (S_half - 64.0f * pr);
    } else {
        // ================= NEAR half-tile =================
        int m    = bid - n_far;
        int chal = m & 1;          // which 64-col half of the tile
        m >>= 1;
        int dti = 0;
        while (m >= T - dti) { m -= T - dti; dti++; }
        int tj = m;
        int ti = tj + dti;

        const int i0 = ti * TILE;
        const int j0 = tj * TILE + chal * 64;

        if (tid < 64) {
            int jg = j0 + tid;
            sm_pc[tid]  = p[jg];
            sm_aux[tid] = -A4 * (float)jg;
        }
        __syncthreads();

        const int   row = tid & (TILE - 1);
        const int   ch  = tid >> 7;          // 0 or 1 -> 32-col sub-half
        const float pr  = p[i0 + row];
        const float r4  = A4 * (float)(i0 + row);

        const float4* pc4 = (const float4*)(sm_pc  + ch * 32);
        const float4* c44 = (const float4*)(sm_aux + ch * 32);

        float acc = 0.0f, accc = 0.0f;

        if (dti != 0) {
            // all pairs valid (i > j)
            #pragma unroll
            for (int g = 0; g < 8; ++g) {
                float4 nn = pc4[g];
                float4 cc = c44[g];
                {
                    float d = pr - nn.x, s = r4 + cc.x;
                    float e = fmaf(-1.5f, s, d);
                    acc += fmaxf(fabsf(e) - s, 0.0f);
                    if (d < 0.0f) accc += s;
                }
                {
                    float d = pr - nn.y, s = r4 + cc.y;
                    float e = fmaf(-1.5f, s, d);
                    acc += fmaxf(fabsf(e) - s, 0.0f);
                    if (d < 0.0f) accc += s;
                }
                {
                    float d = pr - nn.z, s = r4 + cc.z;
                    float e = fmaf(-1.5f, s, d);
                    acc += fmaxf(fabsf(e) - s, 0.0f);
                    if (d < 0.0f) accc += s;
                }
                {
                    float d = pr - nn.w, s = r4 + cc.w;
                    float e = fmaf(-1.5f, s, d);
                    acc += fmaxf(fabsf(e) - s, 0.0f);
                    if (d < 0.0f) accc += s;
                }
            }
        } else {
            // diagonal tile: keep i >= j  <=>  s >= 0 (s exact; s=0 harmless)
            #pragma unroll
            for (int g = 0; g < 8; ++g) {
                float4 nn = pc4[g];
                float4 cc = c44[g];
                {
                    float d = pr - nn.x, s = r4 + cc.x;
                    float e = fmaf(-1.5f, s, d);
                    float h = fmaxf(fabsf(e) - s, 0.0f);
                    if (s >= 0.0f) { acc += h; if (d < 0.0f) accc += s; }
                }
                {
                    float d = pr - nn.y, s = r4 + cc.y;
                    float e = fmaf(-1.5f, s, d);
                    float h = fmaxf(fabsf(e) - s, 0.0f);
                    if (s >= 0.0f) { acc += h; if (d < 0.0f) accc += s; }
                }
                {
                    float d = pr - nn.z, s = r4 + cc.z;
                    float e = fmaf(-1.5f, s, d);
                    float h = fmaxf(fabsf(e) - s, 0.0f);
                    if (s >= 0.0f) { acc += h; if (d < 0.0f) accc += s; }
                }
                {
                    float d = pr - nn.w, s = r4 + cc.w;
                    float e = fmaf(-1.5f, s, d);
                    float h = fmaxf(fabsf(e) - s, 0.0f);
                    if (s >= 0.0f) { acc += h; if (d < 0.0f) accc += s; }
                }
            }
        }
        total = fmaf(-0.5f, accc, acc);
    }

    // Block reduction
    #pragma unroll
    for (int off = 16; off > 0; off >>= 1)
        total += __shfl_xor_sync(0xFFFFFFFFu, total, off);
    __syncthreads();   // protect sm_red reuse (far half-sums)
    if ((tid & 31) == 0) sm_red[tid >> 5] = total;
    __syncthreads();

    if (tid == 0) {
        float v = 0.0f;
        #pragma unroll
        for (int w = 0; w < THREADS / 32; ++w) v += sm_red[w];

        atomicAdd(&g_acc, (double)v);
        __threadfence();
        unsigned old = atomicInc(&g_count, (unsigned)(n_blocks - 1));
        if (old == (unsigned)(n_blocks - 1)) {
            double tot = *((volatile double*)&g_acc);
            out[0] = (float)(tot / ((double)n * (double)n));
            g_acc = 0.0;   // reset for next graph replay
        }
    }
}

extern "C" void kernel_launch(void* const* d_in, const int* in_sizes, int n_in,
                              void* d_out, int out_size)
{
    const float* p  = (const float*)d_in[0];   // predictions (N,1) fp32
    const float* zs = (const float*)d_in[1];   // z_spacing scalar
    const float* ns = (const float*)d_in[2];   // nth_slice scalar
    float* out = (float*)d_out;

    const int n  = in_sizes[0];
    const int T  = n / TILE;                         // 64
    const int Tp = T - DTI_FAR;                      // 58
    const int n_far  = Tp * (Tp + 1) / 2;            // 1711
    const int n_near = T * (T + 1) / 2 - n_far;      // 369
    const int n_blocks = n_far + 2 * n_near;         // 2449

    depth_loss_fused<<<n_blocks, THREADS>>>(p, zs, ns, out, n, n_blocks, n_far, T);
}